// round 14
// baseline (speedup 1.0000x reference)
#include <cuda_runtime.h>
#include <cuda_bf16.h>

// y = (x + 1) * 2/3 ; if y > 0 then y -= 5
// FINAL — roofline-verified over 13 rounds.
// CTA-contiguous exact-fit, MLP=4 per thread, paired ld/ld/st/st.
// 16384 blocks x 256 threads; block b owns float4s [b*1024, (b+1)*1024).
// Measured: kernel 73.8-74.7us, DRAM 81-82.3% (6.44-6.52 TB/s), dur_us ~82.
// Model: 512MB mandatory traffic / ~6.5 TB/s achieved mixed R/W HBM
// ceiling (deficit vs 8TB/s spec = read/write bus turnaround).
// Proven non-levers: unroll {2,4,8}, grid {1184..16384}, CTA {256,512},
// ld cache .cs, st cache {.cs,.wt}, strided vs contiguous layout,
// ld/st interleaving — all neutral or negative vs this configuration.

__device__ __forceinline__ float f(float x) {
    const float c = 2.0f / 3.0f;
    float y = fmaf(x, c, c);        // (x+1)*2/3 == x*c + c
    return y > 0.0f ? y - 5.0f : y; // branchless
}

__device__ __forceinline__ float4 f4(float4 a) {
    return make_float4(f(a.x), f(a.y), f(a.z), f(a.w));
}

__global__ void __launch_bounds__(256, 8) ew_exact(const float4* __restrict__ in,
                                                   float4* __restrict__ out) {
    int base = blockIdx.x * 1024 + threadIdx.x;
    float4 a0 = in[base];
    float4 a1 = in[base + 256];
    out[base]       = f4(a0);
    out[base + 256] = f4(a1);
    float4 a2 = in[base + 512];
    float4 a3 = in[base + 768];
    out[base + 512] = f4(a2);
    out[base + 768] = f4(a3);
}

// Generic fallback (any size).
__global__ void __launch_bounds__(256, 8) ew_generic(const float4* __restrict__ in,
                                                     float4* __restrict__ out,
                                                     int n4) {
    int i = blockIdx.x * blockDim.x + threadIdx.x;
    int stride = gridDim.x * blockDim.x;
    for (; i + 3 * stride < n4; i += 4 * stride) {
        float4 a0 = in[i];
        float4 a1 = in[i + stride];
        float4 a2 = in[i + 2 * stride];
        float4 a3 = in[i + 3 * stride];
        out[i]              = f4(a0);
        out[i + stride]     = f4(a1);
        out[i + 2 * stride] = f4(a2);
        out[i + 3 * stride] = f4(a3);
    }
    for (; i < n4; i += stride) {
        out[i] = f4(in[i]);
    }
}

extern "C" void kernel_launch(void* const* d_in, const int* in_sizes, int n_in,
                              void* d_out, int out_size) {
    const float* x = (const float*)d_in[0];
    float* y = (float*)d_out;
    int n = in_sizes[0];          // 67108864
    const int threads = 256;

    if ((n & 3) == 0) {
        int n4 = n >> 2;          // 16777216
        if ((n4 & 1023) == 0) {   // exact multiple of 1024 float4 per block
            int blocks = n4 >> 10;             // 16384
            ew_exact<<<blocks, threads>>>((const float4*)x, (float4*)y);
            return;
        }
        ew_generic<<<148 * 8 * 4, threads>>>((const float4*)x, (float4*)y, n4);
        return;
    }
    ew_generic<<<148 * 8 * 4, threads>>>((const float4*)x, (float4*)y, n / 4);
}

// round 15
// speedup vs baseline: 1.0012x; 1.0012x over previous
#include <cuda_runtime.h>
#include <cuda_bf16.h>

// y = (x + 1) * 2/3 ; if y > 0 then y -= 5
// FINAL — roofline-verified over 14 rounds.
// CTA-contiguous exact-fit, MLP=4 per thread, paired ld/ld/st/st.
// 16384 blocks x 256 threads; block b owns float4s [b*1024, (b+1)*1024).
// Measured (5 identical-binary runs): kernel 73.8-74.7us, DRAM 81-82.3%
// (6.44-6.52 TB/s), dur_us 81.95-82.4.
// Model: 512MB mandatory traffic / ~6.5 TB/s achieved mixed R/W HBM
// ceiling (deficit vs 8TB/s spec = read/write bus turnaround).
// Proven non-levers: unroll {2,4,8}, grid {1184..16384}, CTA {256,512},
// ld cache .cs, st cache {.cs,.wt}, strided vs contiguous layout,
// ld/st interleaving — all neutral or negative vs this configuration.

__device__ __forceinline__ float f(float x) {
    const float c = 2.0f / 3.0f;
    float y = fmaf(x, c, c);        // (x+1)*2/3 == x*c + c
    return y > 0.0f ? y - 5.0f : y; // branchless
}

__device__ __forceinline__ float4 f4(float4 a) {
    return make_float4(f(a.x), f(a.y), f(a.z), f(a.w));
}

__global__ void __launch_bounds__(256, 8) ew_exact(const float4* __restrict__ in,
                                                   float4* __restrict__ out) {
    int base = blockIdx.x * 1024 + threadIdx.x;
    float4 a0 = in[base];
    float4 a1 = in[base + 256];
    out[base]       = f4(a0);
    out[base + 256] = f4(a1);
    float4 a2 = in[base + 512];
    float4 a3 = in[base + 768];
    out[base + 512] = f4(a2);
    out[base + 768] = f4(a3);
}

// Generic fallback (any size).
__global__ void __launch_bounds__(256, 8) ew_generic(const float4* __restrict__ in,
                                                     float4* __restrict__ out,
                                                     int n4) {
    int i = blockIdx.x * blockDim.x + threadIdx.x;
    int stride = gridDim.x * blockDim.x;
    for (; i + 3 * stride < n4; i += 4 * stride) {
        float4 a0 = in[i];
        float4 a1 = in[i + stride];
        float4 a2 = in[i + 2 * stride];
        float4 a3 = in[i + 3 * stride];
        out[i]              = f4(a0);
        out[i + stride]     = f4(a1);
        out[i + 2 * stride] = f4(a2);
        out[i + 3 * stride] = f4(a3);
    }
    for (; i < n4; i += stride) {
        out[i] = f4(in[i]);
    }
}

extern "C" void kernel_launch(void* const* d_in, const int* in_sizes, int n_in,
                              void* d_out, int out_size) {
    const float* x = (const float*)d_in[0];
    float* y = (float*)d_out;
    int n = in_sizes[0];          // 67108864
    const int threads = 256;

    if ((n & 3) == 0) {
        int n4 = n >> 2;          // 16777216
        if ((n4 & 1023) == 0) {   // exact multiple of 1024 float4 per block
            int blocks = n4 >> 10;             // 16384
            ew_exact<<<blocks, threads>>>((const float4*)x, (float4*)y);
            return;
        }
        ew_generic<<<148 * 8 * 4, threads>>>((const float4*)x, (float4*)y, n4);
        return;
    }
    ew_generic<<<148 * 8 * 4, threads>>>((const float4*)x, (float4*)y, n / 4);
}